// round 1
// baseline (speedup 1.0000x reference)
#include <cuda_runtime.h>

// Var_Net: sigma = rsqrt( exp(-(||z-c_k||^2) * lam_k) @ (W*W) + eps )
// B=262144, K=64, DZ=128, OUT=16 (read from in_sizes for safety)

constexpr int K    = 64;
constexpr int DZ   = 128;
constexpr int OUTD = 16;
constexpr float EPS = 1e-6f;

// ---- packed f32x2 helpers (Blackwell sm_100+) ----
__device__ __forceinline__ unsigned long long pk2(float lo, float hi) {
    unsigned long long r;
    asm("mov.b64 %0, {%1, %2};" : "=l"(r) : "f"(lo), "f"(hi));
    return r;
}
__device__ __forceinline__ void upk2(unsigned long long v, float& lo, float& hi) {
    asm("mov.b64 {%0, %1}, %2;" : "=f"(lo), "=f"(hi) : "l"(v));
}
// d = a * b + d  (packed 2x fp32 in one issue slot)
__device__ __forceinline__ void ffma2(unsigned long long& d,
                                      unsigned long long a,
                                      unsigned long long b) {
    asm("fma.rn.f32x2 %0, %1, %2, %0;" : "+l"(d) : "l"(a), "l"(b));
}

__global__ __launch_bounds__(128)
void varnet_kernel(const float* __restrict__ z,
                   const float* __restrict__ cnts,
                   const float* __restrict__ lams,
                   const float* __restrict__ W,
                   float* __restrict__ out,
                   int B)
{
    __shared__ __align__(16) float s_cnts[K * DZ];   // 32 KB
    __shared__ __align__(16) float s_w2[K * OUTD];   //  4 KB
    __shared__ float s_lam[K];
    __shared__ float s_c2[K];

    const int t = threadIdx.x;

    // Cooperative staging of the small operands (broadcast-reused by every row).
    for (int i = t; i < (K * DZ) / 4; i += 128)
        reinterpret_cast<float4*>(s_cnts)[i] =
            reinterpret_cast<const float4*>(cnts)[i];
    for (int i = t; i < K * OUTD; i += 128) {
        float w = W[i];
        s_w2[i] = w * w;
    }
    if (t < K) s_lam[t] = lams[t];
    __syncthreads();

    if (t < K) {
        float c2 = 0.0f;
        #pragma unroll 8
        for (int d = 0; d < DZ; d++) {
            float c = s_cnts[t * DZ + d];
            c2 = fmaf(c, c, c2);
        }
        s_c2[t] = c2;
    }
    __syncthreads();

    const long long row = (long long)blockIdx.x * 128 + t;
    if (row >= B) return;

    // Load this row's z into 64 packed f32x2 registers, folding ||z||^2.
    unsigned long long zp[DZ / 2];
    unsigned long long zsq = 0ull;
    const float4* zr = reinterpret_cast<const float4*>(z + row * DZ);
    #pragma unroll
    for (int i = 0; i < DZ / 4; i++) {
        float4 v = __ldg(zr + i);
        unsigned long long p0 = pk2(v.x, v.y);
        unsigned long long p1 = pk2(v.z, v.w);
        zp[2 * i]     = p0;
        zp[2 * i + 1] = p1;
        ffma2(zsq, p0, p0);
        ffma2(zsq, p1, p1);
    }
    float zl, zh;
    upk2(zsq, zl, zh);
    const float z2 = zl + zh;

    // Output accumulators (beta), packed.
    unsigned long long op[OUTD / 2];
    #pragma unroll
    for (int j = 0; j < OUTD / 2; j++) op[j] = 0ull;

    for (int k = 0; k < K; k++) {
        const unsigned long long* c =
            reinterpret_cast<const unsigned long long*>(s_cnts + k * DZ);
        // 4 independent packed accumulator chains: ILP covers FFMA lat=4 @ rt=2.
        unsigned long long a0 = 0ull, a1 = 0ull, a2 = 0ull, a3 = 0ull;
        #pragma unroll
        for (int i = 0; i < DZ / 2; i += 4) {
            ffma2(a0, zp[i],     c[i]);
            ffma2(a1, zp[i + 1], c[i + 1]);
            ffma2(a2, zp[i + 2], c[i + 2]);
            ffma2(a3, zp[i + 3], c[i + 3]);
        }
        float x0, x1, y0, y1, u0, u1, v0, v1;
        upk2(a0, x0, x1); upk2(a1, y0, y1);
        upk2(a2, u0, u1); upk2(a3, v0, v1);
        const float dot = ((x0 + x1) + (y0 + y1)) + ((u0 + u1) + (v0 + v1));

        const float t1 = z2 - 2.0f * dot + s_c2[k];
        const float s  = __expf(-s_lam[k] * t1);

        const unsigned long long s2 = pk2(s, s);
        const unsigned long long* w2 =
            reinterpret_cast<const unsigned long long*>(s_w2 + k * OUTD);
        #pragma unroll
        for (int j = 0; j < OUTD / 2; j++)
            ffma2(op[j], s2, w2[j]);
    }

    // sigma = rsqrt(beta + eps), 16 floats -> 4x float4 store.
    float res[OUTD];
    #pragma unroll
    for (int j = 0; j < OUTD / 2; j++) {
        float b0, b1;
        upk2(op[j], b0, b1);
        res[2 * j]     = rsqrtf(b0 + EPS);
        res[2 * j + 1] = rsqrtf(b1 + EPS);
    }
    float4* o = reinterpret_cast<float4*>(out + row * OUTD);
    #pragma unroll
    for (int j = 0; j < OUTD / 4; j++)
        o[j] = reinterpret_cast<const float4*>(res)[j];
}

extern "C" void kernel_launch(void* const* d_in, const int* in_sizes, int n_in,
                              void* d_out, int out_size)
{
    const float* z    = (const float*)d_in[0];  // [B, DZ]
    const float* cnts = (const float*)d_in[1];  // [K, DZ]
    const float* lams = (const float*)d_in[2];  // [K]
    const float* W    = (const float*)d_in[3];  // [K, OUT]
    float* out = (float*)d_out;                 // [B, OUT]

    const int B = in_sizes[0] / DZ;
    const int grid = (B + 127) / 128;
    varnet_kernel<<<grid, 128>>>(z, cnts, lams, W, out, B);
}

// round 2
// speedup vs baseline: 1.7396x; 1.7396x over previous
#include <cuda_runtime.h>

// sigma = rsqrt( exp(-||z-c_k||^2 * lam_k) @ (W*W) + eps )
// B=262144, K=64, DZ=128, OUT=16
constexpr int K    = 64;
constexpr int DZ   = 128;
constexpr int OUTD = 16;
constexpr int ROWS = 64;    // rows per block
constexpr int NT   = 256;   // threads per block
constexpr float EPS = 1e-6f;

// smem layout (bytes)
constexpr int OFF_Z   = 0;                    // float4 [64][33]  (padded rows)
constexpr int SZ_Z    = ROWS * 33 * 16;       // 33792
constexpr int OFF_C   = OFF_Z + SZ_Z;         // float4 [64][32]  (xor-swizzled)
constexpr int SZ_C    = K * 32 * 16;          // 32768
constexpr int OFF_W2T = OFF_C + SZ_C;         // float [16][64]   (transposed W^2)
constexpr int SZ_W2T  = OUTD * K * 4;         // 4096
constexpr int OFF_LAM = OFF_W2T + SZ_W2T;     // float [64]
constexpr int OFF_C2  = OFF_LAM + 256;        // float [64]
constexpr int OFF_Z2  = OFF_C2 + 256;         // float [64]
constexpr int SMEM_BYTES = OFF_Z2 + 256;      // 71424
// V [64][66] overlays the z tile after GEMM (16896 <= 33792)

__device__ __forceinline__ void ffma2(unsigned long long& d,
                                      unsigned long long a,
                                      unsigned long long b) {
    asm("fma.rn.f32x2 %0, %1, %2, %0;" : "+l"(d) : "l"(a), "l"(b));
}
__device__ __forceinline__ float sum2(unsigned long long v) {
    float lo, hi;
    asm("mov.b64 {%0, %1}, %2;" : "=f"(lo), "=f"(hi) : "l"(v));
    return lo + hi;
}

__global__ __launch_bounds__(NT, 2)
void varnet_kernel(const float* __restrict__ z,
                   const float* __restrict__ cnts,
                   const float* __restrict__ lams,
                   const float* __restrict__ W,
                   float* __restrict__ out,
                   int B)
{
    extern __shared__ __align__(16) char smem[];
    float4* s_z4  = reinterpret_cast<float4*>(smem + OFF_Z);
    float4* s_c4  = reinterpret_cast<float4*>(smem + OFF_C);
    float*  s_w2t = reinterpret_cast<float*>(smem + OFF_W2T);
    float*  s_lam = reinterpret_cast<float*>(smem + OFF_LAM);
    float*  s_c2  = reinterpret_cast<float*>(smem + OFF_C2);
    float*  s_z2  = reinterpret_cast<float*>(smem + OFF_Z2);
    float*  s_V   = reinterpret_cast<float*>(smem + OFF_Z);  // overlays z tile

    const int t = threadIdx.x;
    const int row0 = blockIdx.x * ROWS;

    // ---- stage z tile: [64 rows][32 f4], padded stride 33 ----
    {
        const float4* zg = reinterpret_cast<const float4*>(z) +
                           (long long)row0 * (DZ / 4);
        #pragma unroll
        for (int i = t; i < ROWS * 32; i += NT) {
            int r = i >> 5, d4 = i & 31;
            float4 v = make_float4(0.f, 0.f, 0.f, 0.f);
            if (row0 + r < B) v = zg[i];
            s_z4[r * 33 + d4] = v;
        }
    }
    // ---- stage 2*cnts, xor-swizzled ----
    {
        const float4* cg = reinterpret_cast<const float4*>(cnts);
        #pragma unroll
        for (int i = t; i < K * 32; i += NT) {
            int k = i >> 5, d4 = i & 31;
            float4 v = cg[i];
            v.x *= 2.f; v.y *= 2.f; v.z *= 2.f; v.w *= 2.f;
            s_c4[k * 32 + (d4 ^ ((k >> 2) & 7))] = v;
        }
    }
    // ---- stage W^2 transposed [j][k] ----
    #pragma unroll
    for (int i = t; i < K * OUTD; i += NT) {
        int k = i / OUTD, j = i % OUTD;
        float w = W[i];
        s_w2t[j * K + k] = w * w;
    }
    if (t < K) s_lam[t] = lams[t];
    __syncthreads();

    // ---- per-row / per-center squared norms ----
    if (t < 64) {
        const int k = t;
        const float4* cr = s_c4 + k * 32;
        const int m = (k >> 2) & 7;
        float a0 = 0.f, a1 = 0.f, a2 = 0.f, a3 = 0.f;
        #pragma unroll 8
        for (int d4 = 0; d4 < 32; d4++) {
            float4 v = cr[d4 ^ m];
            a0 = fmaf(v.x, v.x, a0); a1 = fmaf(v.y, v.y, a1);
            a2 = fmaf(v.z, v.z, a2); a3 = fmaf(v.w, v.w, a3);
        }
        s_c2[k] = 0.25f * ((a0 + a1) + (a2 + a3));   // stored c' = 2c
    } else if (t < 128) {
        const int r = t - 64;
        const float4* zr = s_z4 + r * 33;
        float a0 = 0.f, a1 = 0.f, a2 = 0.f, a3 = 0.f;
        #pragma unroll 8
        for (int d4 = 0; d4 < 32; d4++) {
            float4 v = zr[d4];
            a0 = fmaf(v.x, v.x, a0); a1 = fmaf(v.y, v.y, a1);
            a2 = fmaf(v.z, v.z, a2); a3 = fmaf(v.w, v.w, a3);
        }
        s_z2[r] = (a0 + a1) + (a2 + a3);
    }
    __syncthreads();

    // ---- GEMM: dot2[r][k] = sum_d z*(2c), thread tile 4x4, f32x2 packed ----
    const int tx = t & 15;      // k tile: 4*tx .. +3
    const int ty = t >> 4;      // row tile: 4*ty .. +3
    const int m = tx & 7;
    const float4* za = s_z4 + 4 * ty * 33;
    const float4* ba = s_c4 + 4 * tx * 32;

    unsigned long long acc[4][4];
    #pragma unroll
    for (int r = 0; r < 4; r++)
        #pragma unroll
        for (int kk = 0; kk < 4; kk++) acc[r][kk] = 0ull;

    #pragma unroll 8
    for (int d4 = 0; d4 < 32; d4++) {
        ulonglong2 a[4], b[4];
        a[0] = *reinterpret_cast<const ulonglong2*>(za + d4);
        a[1] = *reinterpret_cast<const ulonglong2*>(za + 33 + d4);
        a[2] = *reinterpret_cast<const ulonglong2*>(za + 66 + d4);
        a[3] = *reinterpret_cast<const ulonglong2*>(za + 99 + d4);
        const int c = d4 ^ m;
        b[0] = *reinterpret_cast<const ulonglong2*>(ba + c);
        b[1] = *reinterpret_cast<const ulonglong2*>(ba + 32 + c);
        b[2] = *reinterpret_cast<const ulonglong2*>(ba + 64 + c);
        b[3] = *reinterpret_cast<const ulonglong2*>(ba + 96 + c);
        #pragma unroll
        for (int r = 0; r < 4; r++) {
            #pragma unroll
            for (int kk = 0; kk < 4; kk++) {
                ffma2(acc[r][kk], a[r].x, b[kk].x);
                ffma2(acc[r][kk], a[r].y, b[kk].y);
            }
        }
    }

    // ---- epilogue: V = exp(-lam*(z2 + c2 - 2dot)) ----
    const int r0 = 4 * ty, k0 = 4 * tx;
    float Vv[4][4];
    {
        float lamr[4], c2r[4];
        #pragma unroll
        for (int kk = 0; kk < 4; kk++) {
            lamr[kk] = s_lam[k0 + kk];
            c2r[kk]  = s_c2[k0 + kk];
        }
        #pragma unroll
        for (int r = 0; r < 4; r++) {
            const float z2r = s_z2[r0 + r];
            #pragma unroll
            for (int kk = 0; kk < 4; kk++) {
                float t1 = (z2r + c2r[kk]) - sum2(acc[r][kk]);
                Vv[r][kk] = __expf(-lamr[kk] * t1);
            }
        }
    }
    __syncthreads();   // all GEMM reads of z tile done; safe to overlay V
    #pragma unroll
    for (int r = 0; r < 4; r++)
        #pragma unroll
        for (int kk = 0; kk < 4; kk++)
            s_V[(r0 + r) * 66 + (k0 + kk)] = Vv[r][kk];
    __syncthreads();

    // ---- phase 2: beta = V @ W^2 (+eps), sigma = rsqrt ----
    {
        const int row = t & 63;
        const int jg  = t >> 6;      // 4 output groups of 4
        const unsigned long long* vp =
            reinterpret_cast<const unsigned long long*>(s_V + row * 66);
        const unsigned long long* wp =
            reinterpret_cast<const unsigned long long*>(s_w2t);  // [16][32] pairs
        unsigned long long ap0 = 0ull, ap1 = 0ull, ap2 = 0ull, ap3 = 0ull;
        const unsigned long long* w0 = wp + (4 * jg + 0) * 32;
        const unsigned long long* w1 = wp + (4 * jg + 1) * 32;
        const unsigned long long* w2p = wp + (4 * jg + 2) * 32;
        const unsigned long long* w3 = wp + (4 * jg + 3) * 32;
        #pragma unroll 8
        for (int kp = 0; kp < 32; kp++) {
            const unsigned long long v2 = vp[kp];
            ffma2(ap0, v2, w0[kp]);
            ffma2(ap1, v2, w1[kp]);
            ffma2(ap2, v2, w2p[kp]);
            ffma2(ap3, v2, w3[kp]);
        }
        const int grow = row0 + row;
        if (grow < B) {
            float4 o;
            o.x = rsqrtf(sum2(ap0) + EPS);
            o.y = rsqrtf(sum2(ap1) + EPS);
            o.z = rsqrtf(sum2(ap2) + EPS);
            o.w = rsqrtf(sum2(ap3) + EPS);
            reinterpret_cast<float4*>(out)[(long long)grow * 4 + jg] = o;
        }
    }
}

extern "C" void kernel_launch(void* const* d_in, const int* in_sizes, int n_in,
                              void* d_out, int out_size)
{
    const float* z    = (const float*)d_in[0];
    const float* cnts = (const float*)d_in[1];
    const float* lams = (const float*)d_in[2];
    const float* W    = (const float*)d_in[3];
    float* out = (float*)d_out;

    const int B = in_sizes[0] / DZ;
    cudaFuncSetAttribute(varnet_kernel,
                         cudaFuncAttributeMaxDynamicSharedMemorySize, SMEM_BYTES);
    const int grid = (B + ROWS - 1) / ROWS;
    varnet_kernel<<<grid, NT, SMEM_BYTES>>>(z, cnts, lams, W, out, B);
}

// round 4
// speedup vs baseline: 2.3242x; 1.3361x over previous
#include <cuda_runtime.h>
#include <cuda_fp16.h>
#include <cstdint>

// sigma = rsqrt( exp(-||z-c_k||^2 * lam_k) @ (W*W) + eps )
// B=262144, K=64, DZ=128, OUT=16.
// f16-split mma.sync.m16n8k16 (works on plain sm_100 target, no 'a' features).

constexpr int K    = 64;
constexpr int DZ   = 128;
constexpr int OUTD = 16;
constexpr int MT   = 128;    // rows per CTA
constexpr int NTHR = 256;    // 8 warps
constexpr float EPS = 1e-6f;

// padded f16 strides; 136 = 128+8 and 72 = 64+8 are ≡ 8 (mod 64) f16
// -> word-bank = 4*gid + tig for fragment loads: conflict-free.
constexpr int SA = 136;      // A (z) rows stride in f16
constexpr int SB = 136;      // B (2c) rows stride
constexpr int SV = 72;       // V rows stride
constexpr int SW = 72;       // W2 rows stride

// smem byte offsets
constexpr int OFF_AH  = 0;                         // [128][136] f16
constexpr int OFF_AL  = OFF_AH + MT * SA * 2;      // 34816
constexpr int OFF_BH  = OFF_AL + MT * SA * 2;      // 69632   [64][136]
constexpr int OFF_BL  = OFF_BH + K * SB * 2;       // 87040
constexpr int OFF_WH  = OFF_BL + K * SB * 2;       // 104448  [16][72]
constexpr int OFF_WL  = OFF_WH + OUTD * SW * 2;    // 106752
constexpr int OFF_LAM = OFF_WL + OUTD * SW * 2;    // 109056
constexpr int OFF_C2  = OFF_LAM + 256;             // 109312
constexpr int OFF_Z2  = OFF_C2 + 256;              // 109568
constexpr int SMEM_BYTES = OFF_Z2 + 512;           // 110080
// V overlay (after GEMM1): VH at OFF_AH ([128][72] = 18432 B), VL follows.
constexpr int OFF_VH  = OFF_AH;
constexpr int OFF_VL  = OFF_VH + MT * SV * 2;      // 18432  (fits inside A region)

__device__ __forceinline__ void mma16816(float* c, const uint32_t* a,
                                         uint32_t b0, uint32_t b1) {
    asm volatile(
        "mma.sync.aligned.m16n8k16.row.col.f32.f16.f16.f32 "
        "{%0,%1,%2,%3}, {%4,%5,%6,%7}, {%8,%9}, {%0,%1,%2,%3};"
        : "+f"(c[0]), "+f"(c[1]), "+f"(c[2]), "+f"(c[3])
        : "r"(a[0]), "r"(a[1]), "r"(a[2]), "r"(a[3]), "r"(b0), "r"(b1));
}

__device__ __forceinline__ uint32_t split_pack2(float f0, float f1,
                                                uint32_t& lo_pack) {
    // returns (hi(f0), hi(f1)) packed; lo_pack = (lo(f0), lo(f1))
    __half h0 = __float2half_rn(f0);
    __half h1 = __float2half_rn(f1);
    __half l0 = __float2half_rn(f0 - __half2float(h0));
    __half l1 = __float2half_rn(f1 - __half2float(h1));
    lo_pack = (uint32_t)__half_as_ushort(l0) |
              ((uint32_t)__half_as_ushort(l1) << 16);
    return (uint32_t)__half_as_ushort(h0) |
           ((uint32_t)__half_as_ushort(h1) << 16);
}

__global__ __launch_bounds__(NTHR, 2)
void varnet_hmma(const float* __restrict__ z,
                 const float* __restrict__ cnts,
                 const float* __restrict__ lams,
                 const float* __restrict__ W,
                 float* __restrict__ out,
                 int B)
{
    extern __shared__ __align__(16) char smem[];
    float* s_lam = reinterpret_cast<float*>(smem + OFF_LAM);
    float* s_c2  = reinterpret_cast<float*>(smem + OFF_C2);
    float* s_z2  = reinterpret_cast<float*>(smem + OFF_Z2);

    const int t    = threadIdx.x;
    const int wid  = t >> 5;
    const int lane = t & 31;
    const int gid  = lane >> 2;      // 0..7
    const int tig  = lane & 3;       // 0..3
    const int row0 = blockIdx.x * MT;

    // ================= staging: z (all 256 threads) =================
    {
        const int r  = t >> 1;
        const int kh = (t & 1) * 64;
        const long long grow = (long long)row0 + r;
        const float4* zg = reinterpret_cast<const float4*>(z + grow * DZ + kh);
        float z2p = 0.f;
        #pragma unroll
        for (int i = 0; i < 16; i++) {
            float4 v = (grow < B) ? zg[i] : make_float4(0.f, 0.f, 0.f, 0.f);
            z2p = fmaf(v.x, v.x, fmaf(v.y, v.y, fmaf(v.z, v.z, fmaf(v.w, v.w, z2p))));
            const int k = kh + i * 4;
            uint32_t l0, l1;
            uint32_t h0 = split_pack2(v.x, v.y, l0);
            uint32_t h1 = split_pack2(v.z, v.w, l1);
            const int byo = (r * SA + k) * 2;
            *reinterpret_cast<uint32_t*>(smem + OFF_AH + byo)     = h0;
            *reinterpret_cast<uint32_t*>(smem + OFF_AH + byo + 4) = h1;
            *reinterpret_cast<uint32_t*>(smem + OFF_AL + byo)     = l0;
            *reinterpret_cast<uint32_t*>(smem + OFF_AL + byo + 4) = l1;
        }
        z2p += __shfl_xor_sync(0xFFFFFFFFu, z2p, 1);
        if ((t & 1) == 0) s_z2[r] = z2p;
    }

    // ============ staging: 2*cnts (t<128) / W^2 + lam (t>=128) ============
    if (t < 128) {
        const int r  = t >> 1;       // center 0..63
        const int kh = (t & 1) * 64;
        const float4* cg = reinterpret_cast<const float4*>(cnts + r * DZ + kh);
        float c2p = 0.f;
        #pragma unroll
        for (int i = 0; i < 16; i++) {
            float4 v = cg[i];
            c2p = fmaf(v.x, v.x, fmaf(v.y, v.y, fmaf(v.z, v.z, fmaf(v.w, v.w, c2p))));
            const int k = kh + i * 4;
            uint32_t l0, l1;
            uint32_t h0 = split_pack2(2.f * v.x, 2.f * v.y, l0);
            uint32_t h1 = split_pack2(2.f * v.z, 2.f * v.w, l1);
            const int byo = (r * SB + k) * 2;
            *reinterpret_cast<uint32_t*>(smem + OFF_BH + byo)     = h0;
            *reinterpret_cast<uint32_t*>(smem + OFF_BH + byo + 4) = h1;
            *reinterpret_cast<uint32_t*>(smem + OFF_BL + byo)     = l0;
            *reinterpret_cast<uint32_t*>(smem + OFF_BL + byo + 4) = l1;
        }
        c2p += __shfl_xor_sync(0xFFFFFFFFu, c2p, 1);
        if ((t & 1) == 0) s_c2[r] = c2p;
    } else {
        const int tt = t - 128;      // 0..127, 8 W elements each
        #pragma unroll
        for (int i = 0; i < 8; i++) {
            const int idx = tt * 8 + i;          // W is [64][16] row-major
            const int kc = idx >> 4, j = idx & 15;
            float w = W[idx];
            float w2 = w * w;
            __half h = __float2half_rn(w2);
            __half l = __float2half_rn(w2 - __half2float(h));
            const int byo = (j * SW + kc) * 2;
            *reinterpret_cast<uint16_t*>(smem + OFF_WH + byo) = __half_as_ushort(h);
            *reinterpret_cast<uint16_t*>(smem + OFF_WL + byo) = __half_as_ushort(l);
        }
        if (tt < K) s_lam[tt] = lams[tt];
    }
    __syncthreads();

    // ================= GEMM1: dot[128x64] = z . (2c)^T =================
    // warp w: rows 16w..16w+15; 8 n-tiles of 8 cols; 8 k-steps of 16.
    float acc[8][4];
    #pragma unroll
    for (int nt = 0; nt < 8; nt++)
        #pragma unroll
        for (int q = 0; q < 4; q++) acc[nt][q] = 0.f;

    {
        const int rA = 16 * wid + gid;
        const char* pAh = smem + OFF_AH + (rA * SA + tig * 2) * 2;
        const char* pAl = smem + OFF_AL + (rA * SA + tig * 2) * 2;
        const char* pBh = smem + OFF_BH + (gid * SB + tig * 2) * 2;
        const char* pBl = smem + OFF_BL + (gid * SB + tig * 2) * 2;
        constexpr int A_R8 = 8 * SA * 2;    // +8 rows
        constexpr int B_N8 = 8 * SB * 2;    // +8 centers

        #pragma unroll
        for (int s = 0; s < 8; s++) {
            const int ko = s * 16 * 2;      // bytes along k
            uint32_t ah[4], al[4];
            ah[0] = *reinterpret_cast<const uint32_t*>(pAh + ko);
            ah[1] = *reinterpret_cast<const uint32_t*>(pAh + ko + A_R8);
            ah[2] = *reinterpret_cast<const uint32_t*>(pAh + ko + 16);
            ah[3] = *reinterpret_cast<const uint32_t*>(pAh + ko + A_R8 + 16);
            al[0] = *reinterpret_cast<const uint32_t*>(pAl + ko);
            al[1] = *reinterpret_cast<const uint32_t*>(pAl + ko + A_R8);
            al[2] = *reinterpret_cast<const uint32_t*>(pAl + ko + 16);
            al[3] = *reinterpret_cast<const uint32_t*>(pAl + ko + A_R8 + 16);
            #pragma unroll
            for (int nt = 0; nt < 8; nt++) {
                const int bo = nt * B_N8 + ko;
                uint32_t bh0 = *reinterpret_cast<const uint32_t*>(pBh + bo);
                uint32_t bh1 = *reinterpret_cast<const uint32_t*>(pBh + bo + 16);
                uint32_t bl0 = *reinterpret_cast<const uint32_t*>(pBl + bo);
                uint32_t bl1 = *reinterpret_cast<const uint32_t*>(pBl + bo + 16);
                mma16816(acc[nt], ah, bh0, bh1);
                mma16816(acc[nt], ah, bl0, bl1);
                mma16816(acc[nt], al, bh0, bh1);
            }
        }
    }
    __syncthreads();   // all GEMM1 smem reads done; safe to overlay V

    // ===== epilogue 1: V = exp(-lam*(z2+c2-dot)), f16-split into smem =====
    {
        const int rA0 = 16 * wid + gid;
        const float z20 = s_z2[rA0];
        const float z21 = s_z2[rA0 + 8];
        #pragma unroll
        for (int nt = 0; nt < 8; nt++) {
            const int n0 = nt * 8 + tig * 2;
            const float c20 = s_c2[n0], c21 = s_c2[n0 + 1];
            const float lm0 = s_lam[n0], lm1 = s_lam[n0 + 1];
            float v00 = __expf(-lm0 * (z20 + c20 - acc[nt][0]));
            float v01 = __expf(-lm1 * (z20 + c21 - acc[nt][1]));
            float v10 = __expf(-lm0 * (z21 + c20 - acc[nt][2]));
            float v11 = __expf(-lm1 * (z21 + c21 - acc[nt][3]));
            uint32_t l0, l1;
            uint32_t h0 = split_pack2(v00, v01, l0);
            uint32_t h1 = split_pack2(v10, v11, l1);
            const int b0 = (rA0 * SV + n0) * 2;
            const int b1 = ((rA0 + 8) * SV + n0) * 2;
            *reinterpret_cast<uint32_t*>(smem + OFF_VH + b0) = h0;
            *reinterpret_cast<uint32_t*>(smem + OFF_VH + b1) = h1;
            *reinterpret_cast<uint32_t*>(smem + OFF_VL + b0) = l0;
            *reinterpret_cast<uint32_t*>(smem + OFF_VL + b1) = l1;
        }
    }
    __syncthreads();

    // ============ GEMM2: beta[128x16] = V @ W2  (K=64) ============
    float acc2[2][4];
    #pragma unroll
    for (int nt = 0; nt < 2; nt++)
        #pragma unroll
        for (int q = 0; q < 4; q++) acc2[nt][q] = 0.f;
    {
        const int rA = 16 * wid + gid;
        const char* pVh = smem + OFF_VH + (rA * SV + tig * 2) * 2;
        const char* pVl = smem + OFF_VL + (rA * SV + tig * 2) * 2;
        const char* pWh = smem + OFF_WH + (gid * SW + tig * 2) * 2;
        const char* pWl = smem + OFF_WL + (gid * SW + tig * 2) * 2;
        constexpr int V_R8 = 8 * SV * 2;
        constexpr int W_N8 = 8 * SW * 2;

        #pragma unroll
        for (int s = 0; s < 4; s++) {
            const int ko = s * 16 * 2;
            uint32_t vh[4], vl[4];
            vh[0] = *reinterpret_cast<const uint32_t*>(pVh + ko);
            vh[1] = *reinterpret_cast<const uint32_t*>(pVh + ko + V_R8);
            vh[2] = *reinterpret_cast<const uint32_t*>(pVh + ko + 16);
            vh[3] = *reinterpret_cast<const uint32_t*>(pVh + ko + V_R8 + 16);
            vl[0] = *reinterpret_cast<const uint32_t*>(pVl + ko);
            vl[1] = *reinterpret_cast<const uint32_t*>(pVl + ko + V_R8);
            vl[2] = *reinterpret_cast<const uint32_t*>(pVl + ko + 16);
            vl[3] = *reinterpret_cast<const uint32_t*>(pVl + ko + V_R8 + 16);
            #pragma unroll
            for (int nt = 0; nt < 2; nt++) {
                const int bo = nt * W_N8 + ko;
                uint32_t wh0 = *reinterpret_cast<const uint32_t*>(pWh + bo);
                uint32_t wh1 = *reinterpret_cast<const uint32_t*>(pWh + bo + 16);
                uint32_t wl0 = *reinterpret_cast<const uint32_t*>(pWl + bo);
                uint32_t wl1 = *reinterpret_cast<const uint32_t*>(pWl + bo + 16);
                mma16816(acc2[nt], vh, wh0, wh1);
                mma16816(acc2[nt], vh, wl0, wl1);
                mma16816(acc2[nt], vl, wh0, wh1);
            }
        }
    }

    // ============ epilogue 2: sigma = rsqrt(beta+eps), store ============
    {
        const int r0 = 16 * wid + gid;
        const long long g0 = (long long)row0 + r0;
        const long long g1 = g0 + 8;
        #pragma unroll
        for (int nt = 0; nt < 2; nt++) {
            const int j0 = nt * 8 + tig * 2;
            if (g0 < B) {
                float2 o = make_float2(rsqrtf(acc2[nt][0] + EPS),
                                       rsqrtf(acc2[nt][1] + EPS));
                *reinterpret_cast<float2*>(out + g0 * OUTD + j0) = o;
            }
            if (g1 < B) {
                float2 o = make_float2(rsqrtf(acc2[nt][2] + EPS),
                                       rsqrtf(acc2[nt][3] + EPS));
                *reinterpret_cast<float2*>(out + g1 * OUTD + j0) = o;
            }
        }
    }
}

extern "C" void kernel_launch(void* const* d_in, const int* in_sizes, int n_in,
                              void* d_out, int out_size)
{
    const float* z    = (const float*)d_in[0];
    const float* cnts = (const float*)d_in[1];
    const float* lams = (const float*)d_in[2];
    const float* W    = (const float*)d_in[3];
    float* out = (float*)d_out;

    const int B = in_sizes[0] / DZ;
    cudaFuncSetAttribute(varnet_hmma,
                         cudaFuncAttributeMaxDynamicSharedMemorySize, SMEM_BYTES);
    const int grid = (B + MT - 1) / MT;
    varnet_hmma<<<grid, NTHR, SMEM_BYTES>>>(z, cnts, lams, W, out, B);
}